// round 4
// baseline (speedup 1.0000x reference)
#include <cuda_runtime.h>
#include <cuda_bf16.h>
#include <cstdint>

#define EMBED 384
#define HEAD  64
#define BATCH 4
#define TSEQ  4096
#define NQT   64
#define CHUNK 8
#define UNITS_PER_B 288
#define MAXC  8

// Scratch (__device__ globals per alloc rules).
// q/k/v stored as bf16 hi/lo in SWIZZLED 64-row-tile format:
//   elem_idx = tile*4096 + r*64 + ((chunk ^ (r&7))*8) + (col&7),  chunk = col>>3
__device__ __nv_bfloat16 g_qh[BATCH * TSEQ * HEAD];
__device__ __nv_bfloat16 g_ql[BATCH * TSEQ * HEAD];
__device__ __nv_bfloat16 g_kh[BATCH * TSEQ * HEAD];
__device__ __nv_bfloat16 g_kl[BATCH * TSEQ * HEAD];
__device__ __nv_bfloat16 g_vh[BATCH * TSEQ * HEAD];
__device__ __nv_bfloat16 g_vl[BATCH * TSEQ * HEAD];
__device__ __nv_bfloat16 g_wh[3 * EMBED * HEAD];
__device__ __nv_bfloat16 g_wl[3 * EMBED * HEAD];
__device__ float g_opart[BATCH * NQT * MAXC * 64 * 64];
__device__ float g_mpart[BATCH * NQT * MAXC * 64];
__device__ float g_lpart[BATCH * NQT * MAXC * 64];

// ---- tensor-core primitives -----------------------------------------------
__device__ __forceinline__ void ldsm4(uint32_t* r, uint32_t addr) {
    asm volatile("ldmatrix.sync.aligned.m8n8.x4.shared.b16 {%0,%1,%2,%3}, [%4];"
                 : "=r"(r[0]), "=r"(r[1]), "=r"(r[2]), "=r"(r[3]) : "r"(addr));
}
__device__ __forceinline__ void ldsm4t(uint32_t* r, uint32_t addr) {
    asm volatile("ldmatrix.sync.aligned.m8n8.x4.trans.shared.b16 {%0,%1,%2,%3}, [%4];"
                 : "=r"(r[0]), "=r"(r[1]), "=r"(r[2]), "=r"(r[3]) : "r"(addr));
}
__device__ __forceinline__ void mma16816(float* c, const uint32_t* a,
                                         uint32_t b0, uint32_t b1) {
    asm volatile(
        "mma.sync.aligned.m16n8k16.row.col.f32.bf16.bf16.f32 "
        "{%0,%1,%2,%3}, {%4,%5,%6,%7}, {%8,%9}, {%0,%1,%2,%3};"
        : "+f"(c[0]), "+f"(c[1]), "+f"(c[2]), "+f"(c[3])
        : "r"(a[0]), "r"(a[1]), "r"(a[2]), "r"(a[3]), "r"(b0), "r"(b1));
}
__device__ __forceinline__ uint32_t pack_bf16(__nv_bfloat16 a, __nv_bfloat16 b) {
    __nv_bfloat162 t = __halves2bfloat162(a, b);
    return *reinterpret_cast<uint32_t*>(&t);
}
__device__ __forceinline__ void split_pack(float x, float y, uint32_t& hi, uint32_t& lo) {
    __nv_bfloat16 hx = __float2bfloat16_rn(x);
    __nv_bfloat16 hy = __float2bfloat16_rn(y);
    hi = pack_bf16(hx, hy);
    __nv_bfloat16 lx = __float2bfloat16_rn(x - __bfloat162float(hx));
    __nv_bfloat16 ly = __float2bfloat16_rn(y - __bfloat162float(hy));
    lo = pack_bf16(lx, ly);
}
__device__ __forceinline__ void split1(float x, __nv_bfloat16& h, __nv_bfloat16& l) {
    h = __float2bfloat16_rn(x);
    l = __float2bfloat16_rn(x - __bfloat162float(h));
}

// ---------------------------------------------------------------------------
// W conversion: fp32 -> bf16 hi/lo, plain row-major [3][384][64].
// ---------------------------------------------------------------------------
__global__ __launch_bounds__(256) void wconv_kernel(
    const float* __restrict__ Wq,
    const float* __restrict__ Wk,
    const float* __restrict__ Wv)
{
    const int mm = blockIdx.x;
    const float* W = (mm == 0) ? Wq : ((mm == 1) ? Wk : Wv);
    __nv_bfloat16* dh = g_wh + mm * EMBED * HEAD;
    __nv_bfloat16* dl = g_wl + mm * EMBED * HEAD;
    for (int i = threadIdx.x * 4; i < EMBED * HEAD; i += 256 * 4) {
        float4 f = *(const float4*)(W + i);
        __nv_bfloat16 h0, l0, h1, l1, h2, l2, h3, l3;
        split1(f.x, h0, l0); split1(f.y, h1, l1);
        split1(f.z, h2, l2); split1(f.w, h3, l3);
        *(__nv_bfloat162*)(dh + i)     = __halves2bfloat162(h0, h1);
        *(__nv_bfloat162*)(dh + i + 2) = __halves2bfloat162(h2, h3);
        *(__nv_bfloat162*)(dl + i)     = __halves2bfloat162(l0, l1);
        *(__nv_bfloat162*)(dl + i + 2) = __halves2bfloat162(l2, l3);
    }
}

// ---------------------------------------------------------------------------
// Projection: one CTA = 64-row x tile, all 192 output cols (Q|K|V).
// 256 threads = 8 warps: wr = (w&3)*16 rows, wc = w>>2 (96 cols each).
// x converted to hi/lo bf16 ONCE per CTA. W copied (already bf16).
// Output written as bf16 hi/lo in swizzled tile format; Q pre-scaled 0.125.
// ---------------------------------------------------------------------------
#define PXH 0
#define PXL 5120
#define PWH 10240
#define PWL 23040
#define PROJ_SMEM 35840

__global__ __launch_bounds__(256) void proj_kernel(const float* __restrict__ x)
{
    __shared__ char sm[PROJ_SMEM];
    uint32_t sbase = (uint32_t)__cvta_generic_to_shared(sm);

    const int tid  = threadIdx.x;
    const int lane = tid & 31;
    const int w    = tid >> 5;
    const int wr   = (w & 3) * 16;
    const int wc   = w >> 2;            // 0 or 1 (96-col halves)
    const int row0 = blockIdx.x * 64;

    float acc[12][4];
#pragma unroll
    for (int i = 0; i < 12; i++)
#pragma unroll
        for (int j = 0; j < 4; j++) acc[i][j] = 0.f;

    for (int k0 = 0; k0 < EMBED; k0 += 32) {
        __syncthreads();
        // x tile 64x32 fp32 -> hi/lo bf16, stride 80B (conflict-free ldsm).
        {
            int r  = tid >> 2;
            int c4 = tid & 3;
            const float* src = x + (size_t)(row0 + r) * EMBED + k0 + c4 * 8;
            float4 f0 = *(const float4*)src;
            float4 f1 = *(const float4*)(src + 4);
            float v[8] = {f0.x, f0.y, f0.z, f0.w, f1.x, f1.y, f1.z, f1.w};
            __nv_bfloat16 hb[8], lb[8];
#pragma unroll
            for (int j = 0; j < 8; j++) split1(v[j], hb[j], lb[j]);
            int off = r * 80 + c4 * 16;
            *(uint4*)(sm + PXH + off) = *(uint4*)hb;
            *(uint4*)(sm + PXL + off) = *(uint4*)lb;
        }
        // W tile: 32 k-rows x 192 cols hi+lo (bf16 copy), stride 400B.
#pragma unroll
        for (int ii = 0; ii < 6; ii++) {
            int id   = tid + ii * 256;           // 0..1535
            int half = id >= 768;
            int cid  = half ? id - 768 : id;
            int r = cid / 24, c = cid % 24;
            int m = c >> 3, cm = c & 7;
            const __nv_bfloat16* src =
                (half ? g_wl : g_wh) + ((size_t)(m * EMBED + k0 + r) * HEAD + cm * 8);
            char* dst = sm + (half ? PWL : PWH) + r * 400 + c * 16;
            *(uint4*)dst = *(const uint4*)src;
        }
        __syncthreads();

#pragma unroll
        for (int kk = 0; kk < 2; kk++) {
            uint32_t ah[4], al[4];
            int ra = wr + (lane & 15);
            uint32_t aoff = (uint32_t)(ra * 80 + (kk * 2 + (lane >> 4)) * 16);
            ldsm4(ah, sbase + PXH + aoff);
            ldsm4(al, sbase + PXL + aoff);
#pragma unroll
            for (int d2 = 0; d2 < 6; d2++) {
                int rb = kk * 16 + (lane & 7) + ((lane >> 3) & 1) * 8;
                int cb = wc * 12 + d2 * 2 + (lane >> 4);
                uint32_t boff = (uint32_t)(rb * 400 + cb * 16);
                uint32_t bh[4], bl[4];
                ldsm4t(bh, sbase + PWH + boff);
                ldsm4t(bl, sbase + PWL + boff);
                mma16816(acc[2 * d2],     ah, bh[0], bh[1]);
                mma16816(acc[2 * d2],     ah, bl[0], bl[1]);
                mma16816(acc[2 * d2],     al, bh[0], bh[1]);
                mma16816(acc[2 * d2 + 1], ah, bh[2], bh[3]);
                mma16816(acc[2 * d2 + 1], ah, bl[2], bl[3]);
                mma16816(acc[2 * d2 + 1], al, bh[2], bh[3]);
            }
        }
    }

    // Epilogue: split to bf16 hi/lo, store in swizzled tile layout.
    const int rA = wr + (lane >> 2);
    const int rB = rA + 8;
    const size_t tbase = (size_t)blockIdx.x * 4096;
#pragma unroll
    for (int nt = 0; nt < 12; nt++) {
        int gc  = wc * 96 + nt * 8;       // col base of this n8 frag
        int m   = gc >> 6;                // 0=Q, 1=K, 2=V
        int ch  = (gc & 63) >> 3;         // chunk within 64-col matrix
        float sc = (m == 0) ? 0.125f : 1.0f;
        __nv_bfloat16* dh = (m == 0) ? g_qh : ((m == 1) ? g_kh : g_vh);
        __nv_bfloat16* dl = (m == 0) ? g_ql : ((m == 1) ? g_kl : g_vl);
        uint32_t hiA, loA, hiB, loB;
        split_pack(acc[nt][0] * sc, acc[nt][1] * sc, hiA, loA);
        split_pack(acc[nt][2] * sc, acc[nt][3] * sc, hiB, loB);
        size_t iA = tbase + rA * 64 + ((ch ^ (rA & 7)) * 8) + 2 * (lane & 3);
        size_t iB = tbase + rB * 64 + ((ch ^ (rB & 7)) * 8) + 2 * (lane & 3);
        *(uint32_t*)(dh + iA) = hiA;
        *(uint32_t*)(dl + iA) = loA;
        *(uint32_t*)(dh + iB) = hiB;
        *(uint32_t*)(dl + iB) = loB;
    }
}

// ---------------------------------------------------------------------------
// Flash attention, split-KV, tensor-core bf16 3-split.
// Tile fill = straight coalesced 16B copy (global already bf16 + swizzled).
// ---------------------------------------------------------------------------
#define SA_QH 0
#define SA_QL 8192
#define SA_KH 16384
#define SA_KL 24576
#define SA_VH 32768
#define SA_VL 40960
#define ATTN_SMEM 49152

__global__ __launch_bounds__(128, 3) void attn_kernel(float* __restrict__ out)
{
    extern __shared__ char sm[];
    uint32_t sbase = (uint32_t)__cvta_generic_to_shared(sm);

    const int b   = blockIdx.y;
    const int uid = UNITS_PER_B - 1 - (int)blockIdx.x;  // heavy units first
    int rem = uid, band = 0;
    while (rem >= 8 * (band + 1)) { rem -= 8 * (band + 1); band++; }
    const int q  = band * 8 + rem / (band + 1);
    const int c  = rem % (band + 1);
    const int nc = (q >> 3) + 1;
    const int kt0 = c * CHUNK;
    const int kt1 = min(kt0 + CHUNK - 1, q);

    const int tid  = threadIdx.x;
    const int lane = tid & 31;
    const int w    = tid >> 5;
    const int rw0  = w * 16;

    const size_t qtile = (size_t)(b * NQT + q) * 4096;

    // Q hi/lo copy (8 iters of 16B per thread).
#pragma unroll
    for (int ii = 0; ii < 8; ii++) {
        int id   = tid + ii * 128;             // 0..1023
        int half = id >= 512;
        int cid  = half ? id - 512 : id;
        const __nv_bfloat16* src = (half ? g_ql : g_qh) + qtile + cid * 8;
        *(uint4*)(sm + (half ? SA_QL : SA_QH) + cid * 16) = *(const uint4*)src;
    }

    float O[8][4];
    float m2[2] = {-1e30f, -1e30f}, l2[2] = {0.f, 0.f};
#pragma unroll
    for (int i = 0; i < 8; i++)
#pragma unroll
        for (int j = 0; j < 4; j++) O[i][j] = 0.f;

    for (int kt = kt0; kt <= kt1; kt++) {
        __syncthreads();
        const size_t ktile = (size_t)(b * NQT + kt) * 4096;
        // K hi/lo + V hi/lo copy: 2048 chunks of 16B.
#pragma unroll
        for (int ii = 0; ii < 16; ii++) {
            int id  = tid + ii * 128;          // 0..2047
            int sel = id >> 9;                 // 0..3: KH,KL,VH,VL
            int cid = id & 511;
            const __nv_bfloat16* src =
                ((sel == 0) ? g_kh : (sel == 1) ? g_kl : (sel == 2) ? g_vh : g_vl)
                + ktile + cid * 8;
            int dst = ((sel == 0) ? SA_KH : (sel == 1) ? SA_KL
                                          : (sel == 2) ? SA_VH : SA_VL) + cid * 16;
            *(uint4*)(sm + dst) = *(const uint4*)src;
        }
        __syncthreads();

        // ---- S = Q @ K^T (3-pass bf16) ----
        float S[8][4];
#pragma unroll
        for (int i = 0; i < 8; i++)
#pragma unroll
            for (int j = 0; j < 4; j++) S[i][j] = 0.f;

#pragma unroll
        for (int kk = 0; kk < 4; kk++) {
            uint32_t ah[4], al[4];
            int ra = rw0 + (lane & 15);
            uint32_t ca = (uint32_t)(kk * 2 + (lane >> 4));
            uint32_t aoff = (uint32_t)(ra * 128 + ((ca ^ (uint32_t)(ra & 7)) * 16));
            ldsm4(ah, sbase + SA_QH + aoff);
            ldsm4(al, sbase + SA_QL + aoff);
#pragma unroll
            for (int n2 = 0; n2 < 4; n2++) {
                int rb = n2 * 16 + (lane & 7) + ((lane >> 4) ? 8 : 0);
                uint32_t cb = (uint32_t)(kk * 2 + ((lane >> 3) & 1));
                uint32_t boff = (uint32_t)(rb * 128 + ((cb ^ (uint32_t)(rb & 7)) * 16));
                uint32_t bh[4], bl[4];
                ldsm4(bh, sbase + SA_KH + boff);
                ldsm4(bl, sbase + SA_KL + boff);
                mma16816(S[2 * n2],     ah, bh[0], bh[1]);
                mma16816(S[2 * n2],     ah, bl[0], bl[1]);
                mma16816(S[2 * n2],     al, bh[0], bh[1]);
                mma16816(S[2 * n2 + 1], ah, bh[2], bh[3]);
                mma16816(S[2 * n2 + 1], ah, bl[2], bl[3]);
                mma16816(S[2 * n2 + 1], al, bh[2], bh[3]);
            }
        }

        if (kt == q) {  // diagonal tile: causal mask
            int rl0 = rw0 + (lane >> 2);
            int cb  = 2 * (lane & 3);
#pragma unroll
            for (int nt = 0; nt < 8; nt++) {
#pragma unroll
                for (int j = 0; j < 4; j++) {
                    int col = nt * 8 + cb + (j & 1);
                    int row = rl0 + ((j >= 2) ? 8 : 0);
                    if (col > row) S[nt][j] = -1e30f;
                }
            }
        }

        // ---- online softmax ----
#pragma unroll
        for (int h = 0; h < 2; h++) {
            float mx = -1e30f;
#pragma unroll
            for (int nt = 0; nt < 8; nt++)
                mx = fmaxf(mx, fmaxf(S[nt][2 * h], S[nt][2 * h + 1]));
            mx = fmaxf(mx, __shfl_xor_sync(0xffffffffu, mx, 1));
            mx = fmaxf(mx, __shfl_xor_sync(0xffffffffu, mx, 2));
            float mn    = fmaxf(m2[h], mx);
            float alpha = __expf(m2[h] - mn);
            float sum   = 0.f;
#pragma unroll
            for (int nt = 0; nt < 8; nt++) {
                float p0 = __expf(S[nt][2 * h]     - mn);
                float p1 = __expf(S[nt][2 * h + 1] - mn);
                S[nt][2 * h] = p0; S[nt][2 * h + 1] = p1;
                sum += p0 + p1;
            }
            sum += __shfl_xor_sync(0xffffffffu, sum, 1);
            sum += __shfl_xor_sync(0xffffffffu, sum, 2);
            l2[h] = l2[h] * alpha + sum;
            m2[h] = mn;
#pragma unroll
            for (int nt = 0; nt < 8; nt++) {
                O[nt][2 * h] *= alpha; O[nt][2 * h + 1] *= alpha;
            }
        }

        // ---- O += P @ V (3-pass bf16) ----
#pragma unroll
        for (int kk = 0; kk < 4; kk++) {
            uint32_t ph[4], pl[4];
            split_pack(S[2 * kk][0],     S[2 * kk][1],     ph[0], pl[0]);
            split_pack(S[2 * kk][2],     S[2 * kk][3],     ph[1], pl[1]);
            split_pack(S[2 * kk + 1][0], S[2 * kk + 1][1], ph[2], pl[2]);
            split_pack(S[2 * kk + 1][2], S[2 * kk + 1][3], ph[3], pl[3]);
#pragma unroll
            for (int d2 = 0; d2 < 4; d2++) {
                int rv = kk * 16 + (lane & 7) + ((lane >> 3) & 1) * 8;
                uint32_t cv = (uint32_t)(d2 * 2 + (lane >> 4));
                uint32_t voff = (uint32_t)(rv * 128 + ((cv ^ (uint32_t)(rv & 7)) * 16));
                uint32_t vh[4], vl[4];
                ldsm4t(vh, sbase + SA_VH + voff);
                ldsm4t(vl, sbase + SA_VL + voff);
                mma16816(O[2 * d2],     ph, vh[0], vh[1]);
                mma16816(O[2 * d2],     ph, vl[0], vl[1]);
                mma16816(O[2 * d2],     pl, vh[0], vh[1]);
                mma16816(O[2 * d2 + 1], ph, vh[2], vh[3]);
                mma16816(O[2 * d2 + 1], ph, vl[2], vl[3]);
                mma16816(O[2 * d2 + 1], pl, vh[2], vh[3]);
            }
        }
    }

    const int rA = rw0 + (lane >> 2);
    const int rB = rA + 8;
    if (nc == 1) {
        float* Ob = out + ((size_t)b * TSEQ + (size_t)q * 64) * HEAD;
        float i0 = 1.0f / l2[0], i1 = 1.0f / l2[1];
#pragma unroll
        for (int nt = 0; nt < 8; nt++) {
            int cc = nt * 8 + 2 * (lane & 3);
            *(float2*)&Ob[rA * HEAD + cc] = make_float2(O[nt][0] * i0, O[nt][1] * i0);
            *(float2*)&Ob[rB * HEAD + cc] = make_float2(O[nt][2] * i1, O[nt][3] * i1);
        }
    } else {
        float* gp = g_opart + (((size_t)(b * NQT + q) * MAXC + c) * 4096);
#pragma unroll
        for (int nt = 0; nt < 8; nt++) {
            int cc = nt * 8 + 2 * (lane & 3);
            *(float2*)&gp[rA * 64 + cc] = make_float2(O[nt][0], O[nt][1]);
            *(float2*)&gp[rB * 64 + cc] = make_float2(O[nt][2], O[nt][3]);
        }
        if ((lane & 3) == 0) {
            float* gm = g_mpart + ((size_t)(b * NQT + q) * MAXC + c) * 64;
            float* gl = g_lpart + ((size_t)(b * NQT + q) * MAXC + c) * 64;
            gm[rA] = m2[0]; gm[rB] = m2[1];
            gl[rA] = l2[0]; gl[rB] = l2[1];
        }
    }
}

// ---------------------------------------------------------------------------
// Combine split-KV partials (q tiles with nc >= 2).
// ---------------------------------------------------------------------------
__global__ __launch_bounds__(128) void combine_kernel(float* __restrict__ out)
{
    const int q  = 8 + blockIdx.x;
    const int b  = blockIdx.y;
    const int nc = (q >> 3) + 1;
    const int tid = threadIdx.x;
    const int r  = tid >> 1;
    const int dh = (tid & 1) * 32;

    const size_t base = (size_t)(b * NQT + q) * MAXC;
    float mc[MAXC], lc[MAXC];
    float mstar = -1e30f;
    for (int cgi = 0; cgi < nc; cgi++) {
        mc[cgi] = g_mpart[(base + cgi) * 64 + r];
        lc[cgi] = g_lpart[(base + cgi) * 64 + r];
        mstar = fmaxf(mstar, mc[cgi]);
    }
    float wgt[MAXC], lstar = 0.f;
    for (int cgi = 0; cgi < nc; cgi++) {
        wgt[cgi] = __expf(mc[cgi] - mstar);
        lstar += lc[cgi] * wgt[cgi];
    }
    const float inv = 1.0f / lstar;

    float* Ob = out + ((size_t)b * TSEQ + (size_t)q * 64 + r) * HEAD + dh;
#pragma unroll
    for (int j4 = 0; j4 < 8; j4++) {
        float4 acc = make_float4(0.f, 0.f, 0.f, 0.f);
        for (int cgi = 0; cgi < nc; cgi++) {
            const float* gp = g_opart + (base + cgi) * 4096 + r * 64 + dh + j4 * 4;
            float4 p = *(const float4*)gp;
            acc.x += wgt[cgi] * p.x; acc.y += wgt[cgi] * p.y;
            acc.z += wgt[cgi] * p.z; acc.w += wgt[cgi] * p.w;
        }
        *(float4*)&Ob[j4 * 4] =
            make_float4(acc.x * inv, acc.y * inv, acc.z * inv, acc.w * inv);
    }
}

// ---------------------------------------------------------------------------
extern "C" void kernel_launch(void* const* d_in, const int* in_sizes, int n_in,
                              void* d_out, int out_size)
{
    (void)in_sizes; (void)n_in; (void)out_size;
    const float* x  = (const float*)d_in[0];
    const float* Wq = (const float*)d_in[1];
    const float* Wk = (const float*)d_in[2];
    const float* Wv = (const float*)d_in[3];
    float* out = (float*)d_out;

    wconv_kernel<<<3, 256>>>(Wq, Wk, Wv);
    proj_kernel<<<(BATCH * TSEQ) / 64, 256>>>(x);

    cudaFuncSetAttribute(attn_kernel, cudaFuncAttributeMaxDynamicSharedMemorySize, ATTN_SMEM);
    dim3 grid(UNITS_PER_B, BATCH);
    attn_kernel<<<grid, 128, ATTN_SMEM>>>(out);

    dim3 cgrid(NQT - 8, BATCH);
    combine_kernel<<<cgrid, 128>>>(out);
}

// round 5
// speedup vs baseline: 1.4228x; 1.4228x over previous
#include <cuda_runtime.h>
#include <cuda_bf16.h>
#include <cstdint>

#define EMBED 384
#define HEAD  64
#define BATCH 4
#define TSEQ  4096
#define NQT   64
#define CHUNK 8
#define UNITS_PER_B 288
#define MAXC  8

// Scratch (__device__ globals per alloc rules).
__device__ float g_q[BATCH * TSEQ * HEAD];
__device__ float g_k[BATCH * TSEQ * HEAD];
__device__ float g_v[BATCH * TSEQ * HEAD];
__device__ float g_opart[BATCH * NQT * MAXC * 64 * 64];
__device__ float g_mpart[BATCH * NQT * MAXC * 64];
__device__ float g_lpart[BATCH * NQT * MAXC * 64];

// ---- tensor-core primitives -----------------------------------------------
__device__ __forceinline__ void ldsm4(uint32_t* r, uint32_t addr) {
    asm volatile("ldmatrix.sync.aligned.m8n8.x4.shared.b16 {%0,%1,%2,%3}, [%4];"
                 : "=r"(r[0]), "=r"(r[1]), "=r"(r[2]), "=r"(r[3]) : "r"(addr));
}
__device__ __forceinline__ void ldsm4t(uint32_t* r, uint32_t addr) {
    asm volatile("ldmatrix.sync.aligned.m8n8.x4.trans.shared.b16 {%0,%1,%2,%3}, [%4];"
                 : "=r"(r[0]), "=r"(r[1]), "=r"(r[2]), "=r"(r[3]) : "r"(addr));
}
__device__ __forceinline__ void mma16816(float* c, const uint32_t* a,
                                         uint32_t b0, uint32_t b1) {
    asm volatile(
        "mma.sync.aligned.m16n8k16.row.col.f32.bf16.bf16.f32 "
        "{%0,%1,%2,%3}, {%4,%5,%6,%7}, {%8,%9}, {%0,%1,%2,%3};"
        : "+f"(c[0]), "+f"(c[1]), "+f"(c[2]), "+f"(c[3])
        : "r"(a[0]), "r"(a[1]), "r"(a[2]), "r"(a[3]), "r"(b0), "r"(b1));
}
__device__ __forceinline__ uint32_t pack_bf16(__nv_bfloat16 a, __nv_bfloat16 b) {
    __nv_bfloat162 t = __halves2bfloat162(a, b);
    return *reinterpret_cast<uint32_t*>(&t);
}
// Split (x,y) into hi/lo bf16x2 pairs (x in low half = element 0).
__device__ __forceinline__ void split_pack(float x, float y, uint32_t& hi, uint32_t& lo) {
    __nv_bfloat16 hx = __float2bfloat16_rn(x);
    __nv_bfloat16 hy = __float2bfloat16_rn(y);
    hi = pack_bf16(hx, hy);
    __nv_bfloat16 lx = __float2bfloat16_rn(x - __bfloat162float(hx));
    __nv_bfloat16 ly = __float2bfloat16_rn(y - __bfloat162float(hy));
    lo = pack_bf16(lx, ly);
}

// Fill a 64x64 tile (row-major, ld=64) into swizzled bf16 hi/lo arrays.
// Swizzle: 16B chunk c of row r stored at chunk (c ^ (r&7)). 512 chunks total.
__device__ __forceinline__ void fill64(char* dh, char* dl, const float* src,
                                       float scale, int tid) {
#pragma unroll
    for (int it = 0; it < 4; it++) {
        int id = tid + it * 128;
        int r = id >> 3, c = id & 7;
        float4 f0 = *(const float4*)(src + r * 64 + c * 8);
        float4 f1 = *(const float4*)(src + r * 64 + c * 8 + 4);
        float v[8] = {f0.x * scale, f0.y * scale, f0.z * scale, f0.w * scale,
                      f1.x * scale, f1.y * scale, f1.z * scale, f1.w * scale};
        __nv_bfloat16 hb[8], lb[8];
#pragma unroll
        for (int j = 0; j < 8; j++) {
            hb[j] = __float2bfloat16_rn(v[j]);
            lb[j] = __float2bfloat16_rn(v[j] - __bfloat162float(hb[j]));
        }
        int off = r * 128 + ((c ^ (r & 7)) * 16);
        *(uint4*)(dh + off) = *(uint4*)hb;
        *(uint4*)(dl + off) = *(uint4*)lb;
    }
}

// ---------------------------------------------------------------------------
// Projection: y = x @ W, tensor-core bf16 3-split. Grid (256 row-tiles, 3 mats).
// 128 threads = 4 warps, each warp 16 rows x 64 cols.  (R3-proven version)
// ---------------------------------------------------------------------------
#define PX_H 0
#define PX_L 5120
#define PW_H 10240
#define PW_L 14336
#define PROJ_SMEM 18432

__global__ __launch_bounds__(128) void proj_kernel(
    const float* __restrict__ x,
    const float* __restrict__ Wq,
    const float* __restrict__ Wk,
    const float* __restrict__ Wv)
{
    __shared__ char sm[PROJ_SMEM];
    uint32_t sbase = (uint32_t)__cvta_generic_to_shared(sm);

    const int tid  = threadIdx.x;
    const int lane = tid & 31;
    const int w    = tid >> 5;
    const int rw0  = w * 16;
    const int row0 = blockIdx.x * 64;
    const int mm   = blockIdx.y;
    const float* W = (mm == 0) ? Wq : ((mm == 1) ? Wk : Wv);
    float* g       = (mm == 0) ? g_q : ((mm == 1) ? g_k : g_v);

    float acc[8][4];
#pragma unroll
    for (int i = 0; i < 8; i++)
#pragma unroll
        for (int j = 0; j < 4; j++) acc[i][j] = 0.f;

    for (int k0 = 0; k0 < EMBED; k0 += 32) {
        __syncthreads();
        // X tile: 64 rows x 32 k, stride 40 bf16 (80B).
#pragma unroll
        for (int it = 0; it < 2; it++) {
            int id = tid + it * 128;           // 0..255
            int r = id >> 2, c = id & 3;
            const float* src = x + (size_t)(row0 + r) * EMBED + k0 + c * 8;
            float4 f0 = *(const float4*)src;
            float4 f1 = *(const float4*)(src + 4);
            float v[8] = {f0.x, f0.y, f0.z, f0.w, f1.x, f1.y, f1.z, f1.w};
            __nv_bfloat16 hb[8], lb[8];
#pragma unroll
            for (int j = 0; j < 8; j++) {
                hb[j] = __float2bfloat16_rn(v[j]);
                lb[j] = __float2bfloat16_rn(v[j] - __bfloat162float(hb[j]));
            }
            int off = r * 80 + c * 16;
            *(uint4*)(sm + PX_H + off) = *(uint4*)hb;
            *(uint4*)(sm + PX_L + off) = *(uint4*)lb;
        }
        // W tile: 32 k-rows x 64 n, stride 128B, XOR swizzle.
#pragma unroll
        for (int it = 0; it < 2; it++) {
            int id = tid + it * 128;
            int r = id >> 3, c = id & 7;       // r 0..31
            const float* src = W + (size_t)(k0 + r) * HEAD + c * 8;
            float4 f0 = *(const float4*)src;
            float4 f1 = *(const float4*)(src + 4);
            float v[8] = {f0.x, f0.y, f0.z, f0.w, f1.x, f1.y, f1.z, f1.w};
            __nv_bfloat16 hb[8], lb[8];
#pragma unroll
            for (int j = 0; j < 8; j++) {
                hb[j] = __float2bfloat16_rn(v[j]);
                lb[j] = __float2bfloat16_rn(v[j] - __bfloat162float(hb[j]));
            }
            int off = r * 128 + ((c ^ (r & 7)) * 16);
            *(uint4*)(sm + PW_H + off) = *(uint4*)hb;
            *(uint4*)(sm + PW_L + off) = *(uint4*)lb;
        }
        __syncthreads();

#pragma unroll
        for (int kk = 0; kk < 2; kk++) {
            uint32_t ah[4], al[4];
            int ra = rw0 + (lane & 15);
            uint32_t aoff = (uint32_t)(ra * 80 + (kk * 2 + (lane >> 4)) * 16);
            ldsm4(ah, sbase + PX_H + aoff);
            ldsm4(al, sbase + PX_L + aoff);
#pragma unroll
            for (int d2 = 0; d2 < 4; d2++) {
                int rb = kk * 16 + (lane & 7) + ((lane >> 3) & 1) * 8;
                uint32_t cb = (uint32_t)(d2 * 2 + (lane >> 4));
                uint32_t boff = (uint32_t)(rb * 128 + ((cb ^ (uint32_t)(rb & 7)) * 16));
                uint32_t bh[4], bl[4];
                ldsm4t(bh, sbase + PW_H + boff);
                ldsm4t(bl, sbase + PW_L + boff);
                mma16816(acc[2 * d2],     ah, bh[0], bh[1]);
                mma16816(acc[2 * d2],     ah, bl[0], bl[1]);
                mma16816(acc[2 * d2],     al, bh[0], bh[1]);
                mma16816(acc[2 * d2 + 1], ah, bh[2], bh[3]);
                mma16816(acc[2 * d2 + 1], ah, bl[2], bl[3]);
                mma16816(acc[2 * d2 + 1], al, bh[2], bh[3]);
            }
        }
    }

    const int rA = row0 + rw0 + (lane >> 2);
    const int rB = rA + 8;
#pragma unroll
    for (int nt = 0; nt < 8; nt++) {
        int cc = nt * 8 + 2 * (lane & 3);
        *(float2*)&g[(size_t)rA * HEAD + cc] = make_float2(acc[nt][0], acc[nt][1]);
        *(float2*)&g[(size_t)rB * HEAD + cc] = make_float2(acc[nt][2], acc[nt][3]);
    }
}

// ---------------------------------------------------------------------------
// Flash attention, split-KV, tensor-core bf16 3-split.  (R3-proven version,
// occupancy bumped 3 -> 4: smem 48KB*4 = 192KB <= 228KB, regs capped at 128)
// ---------------------------------------------------------------------------
#define SA_QH 0
#define SA_QL 8192
#define SA_KH 16384
#define SA_KL 24576
#define SA_VH 32768
#define SA_VL 40960
#define ATTN_SMEM 49152

__global__ __launch_bounds__(128, 4) void attn_kernel(float* __restrict__ out)
{
    extern __shared__ char sm[];
    uint32_t sbase = (uint32_t)__cvta_generic_to_shared(sm);

    const int b   = blockIdx.y;
    const int uid = UNITS_PER_B - 1 - (int)blockIdx.x;  // heavy units first
    int rem = uid, band = 0;
    while (rem >= 8 * (band + 1)) { rem -= 8 * (band + 1); band++; }
    const int q  = band * 8 + rem / (band + 1);
    const int c  = rem % (band + 1);
    const int nc = (q >> 3) + 1;
    const int kt0 = c * CHUNK;
    const int kt1 = min(kt0 + CHUNK - 1, q);

    const int tid  = threadIdx.x;
    const int lane = tid & 31;
    const int w    = tid >> 5;
    const int rw0  = w * 16;

    const float* Qb = g_q + ((size_t)b * TSEQ + (size_t)q * 64) * HEAD;
    const float* Kb = g_k + (size_t)b * TSEQ * HEAD;
    const float* Vb = g_v + (size_t)b * TSEQ * HEAD;

    fill64(sm + SA_QH, sm + SA_QL, Qb, 0.125f, tid);   // scale folded into Q

    float O[8][4];
    float m2[2] = {-1e30f, -1e30f}, l2[2] = {0.f, 0.f};
#pragma unroll
    for (int i = 0; i < 8; i++)
#pragma unroll
        for (int j = 0; j < 4; j++) O[i][j] = 0.f;

    for (int kt = kt0; kt <= kt1; kt++) {
        __syncthreads();
        fill64(sm + SA_KH, sm + SA_KL, Kb + (size_t)kt * 64 * HEAD, 1.f, tid);
        fill64(sm + SA_VH, sm + SA_VL, Vb + (size_t)kt * 64 * HEAD, 1.f, tid);
        __syncthreads();

        // ---- S = Q @ K^T (3-pass bf16) ----
        float S[8][4];
#pragma unroll
        for (int i = 0; i < 8; i++)
#pragma unroll
            for (int j = 0; j < 4; j++) S[i][j] = 0.f;

#pragma unroll
        for (int kk = 0; kk < 4; kk++) {
            uint32_t ah[4], al[4];
            int ra = rw0 + (lane & 15);
            uint32_t ca = (uint32_t)(kk * 2 + (lane >> 4));
            uint32_t aoff = (uint32_t)(ra * 128 + ((ca ^ (uint32_t)(ra & 7)) * 16));
            ldsm4(ah, sbase + SA_QH + aoff);
            ldsm4(al, sbase + SA_QL + aoff);
#pragma unroll
            for (int n2 = 0; n2 < 4; n2++) {
                int rb = n2 * 16 + (lane & 7) + ((lane >> 4) ? 8 : 0);
                uint32_t cb = (uint32_t)(kk * 2 + ((lane >> 3) & 1));
                uint32_t boff = (uint32_t)(rb * 128 + ((cb ^ (uint32_t)(rb & 7)) * 16));
                uint32_t bh[4], bl[4];
                ldsm4(bh, sbase + SA_KH + boff);
                ldsm4(bl, sbase + SA_KL + boff);
                mma16816(S[2 * n2],     ah, bh[0], bh[1]);
                mma16816(S[2 * n2],     ah, bl[0], bl[1]);
                mma16816(S[2 * n2],     al, bh[0], bh[1]);
                mma16816(S[2 * n2 + 1], ah, bh[2], bh[3]);
                mma16816(S[2 * n2 + 1], ah, bl[2], bl[3]);
                mma16816(S[2 * n2 + 1], al, bh[2], bh[3]);
            }
        }

        if (kt == q) {  // diagonal tile: causal mask (local coords)
            int rl0 = rw0 + (lane >> 2);
            int cb  = 2 * (lane & 3);
#pragma unroll
            for (int nt = 0; nt < 8; nt++) {
#pragma unroll
                for (int j = 0; j < 4; j++) {
                    int col = nt * 8 + cb + (j & 1);
                    int row = rl0 + ((j >= 2) ? 8 : 0);
                    if (col > row) S[nt][j] = -1e30f;
                }
            }
        }

        // ---- online softmax (rows lane/4 and lane/4+8 of this warp) ----
#pragma unroll
        for (int h = 0; h < 2; h++) {
            float mx = -1e30f;
#pragma unroll
            for (int nt = 0; nt < 8; nt++)
                mx = fmaxf(mx, fmaxf(S[nt][2 * h], S[nt][2 * h + 1]));
            mx = fmaxf(mx, __shfl_xor_sync(0xffffffffu, mx, 1));
            mx = fmaxf(mx, __shfl_xor_sync(0xffffffffu, mx, 2));
            float mn    = fmaxf(m2[h], mx);
            float alpha = __expf(m2[h] - mn);
            float sum   = 0.f;
#pragma unroll
            for (int nt = 0; nt < 8; nt++) {
                float p0 = __expf(S[nt][2 * h]     - mn);
                float p1 = __expf(S[nt][2 * h + 1] - mn);
                S[nt][2 * h] = p0; S[nt][2 * h + 1] = p1;
                sum += p0 + p1;
            }
            sum += __shfl_xor_sync(0xffffffffu, sum, 1);
            sum += __shfl_xor_sync(0xffffffffu, sum, 2);
            l2[h] = l2[h] * alpha + sum;
            m2[h] = mn;
#pragma unroll
            for (int nt = 0; nt < 8; nt++) {
                O[nt][2 * h] *= alpha; O[nt][2 * h + 1] *= alpha;
            }
        }

        // ---- O += P @ V (3-pass bf16); P frags straight from S regs ----
#pragma unroll
        for (int kk = 0; kk < 4; kk++) {
            uint32_t ph[4], pl[4];
            split_pack(S[2 * kk][0],     S[2 * kk][1],     ph[0], pl[0]);
            split_pack(S[2 * kk][2],     S[2 * kk][3],     ph[1], pl[1]);
            split_pack(S[2 * kk + 1][0], S[2 * kk + 1][1], ph[2], pl[2]);
            split_pack(S[2 * kk + 1][2], S[2 * kk + 1][3], ph[3], pl[3]);
#pragma unroll
            for (int d2 = 0; d2 < 4; d2++) {
                int rv = kk * 16 + (lane & 7) + ((lane >> 3) & 1) * 8;
                uint32_t cv = (uint32_t)(d2 * 2 + (lane >> 4));
                uint32_t voff = (uint32_t)(rv * 128 + ((cv ^ (uint32_t)(rv & 7)) * 16));
                uint32_t vh[4], vl[4];
                ldsm4t(vh, sbase + SA_VH + voff);
                ldsm4t(vl, sbase + SA_VL + voff);
                mma16816(O[2 * d2],     ph, vh[0], vh[1]);
                mma16816(O[2 * d2],     ph, vl[0], vl[1]);
                mma16816(O[2 * d2],     pl, vh[0], vh[1]);
                mma16816(O[2 * d2 + 1], ph, vh[2], vh[3]);
                mma16816(O[2 * d2 + 1], ph, vl[2], vl[3]);
                mma16816(O[2 * d2 + 1], pl, vh[2], vh[3]);
            }
        }
    }

    const int rA = rw0 + (lane >> 2);
    const int rB = rA + 8;
    if (nc == 1) {
        float* Ob = out + ((size_t)b * TSEQ + (size_t)q * 64) * HEAD;
        float i0 = 1.0f / l2[0], i1 = 1.0f / l2[1];
#pragma unroll
        for (int nt = 0; nt < 8; nt++) {
            int cc = nt * 8 + 2 * (lane & 3);
            *(float2*)&Ob[rA * HEAD + cc] = make_float2(O[nt][0] * i0, O[nt][1] * i0);
            *(float2*)&Ob[rB * HEAD + cc] = make_float2(O[nt][2] * i1, O[nt][3] * i1);
        }
    } else {
        float* gp = g_opart + (((size_t)(b * NQT + q) * MAXC + c) * 4096);
#pragma unroll
        for (int nt = 0; nt < 8; nt++) {
            int cc = nt * 8 + 2 * (lane & 3);
            *(float2*)&gp[rA * 64 + cc] = make_float2(O[nt][0], O[nt][1]);
            *(float2*)&gp[rB * 64 + cc] = make_float2(O[nt][2], O[nt][3]);
        }
        if ((lane & 3) == 0) {
            float* gm = g_mpart + ((size_t)(b * NQT + q) * MAXC + c) * 64;
            float* gl = g_lpart + ((size_t)(b * NQT + q) * MAXC + c) * 64;
            gm[rA] = m2[0]; gm[rB] = m2[1];
            gl[rA] = l2[0]; gl[rB] = l2[1];
        }
    }
}

// ---------------------------------------------------------------------------
// Combine split-KV partials. 4 CTAs per (q,b) tile (16 rows each) -> 896 CTAs.
// Thread: one row x 8 cols. 8-thread groups read 256B contiguous -> coalesced.
// ---------------------------------------------------------------------------
__global__ __launch_bounds__(128) void combine_kernel(float* __restrict__ out)
{
    const int q  = 8 + blockIdx.x;
    const int b  = blockIdx.y;
    const int rg = blockIdx.z;              // 0..3 row group
    const int nc = (q >> 3) + 1;
    const int tid = threadIdx.x;
    const int r  = rg * 16 + (tid >> 3);    // row 0..63
    const int c8 = (tid & 7) * 8;           // col base

    const size_t base = (size_t)(b * NQT + q) * MAXC;
    float mc[MAXC], lc[MAXC];
    float mstar = -1e30f;
    for (int cgi = 0; cgi < nc; cgi++) {
        mc[cgi] = g_mpart[(base + cgi) * 64 + r];
        lc[cgi] = g_lpart[(base + cgi) * 64 + r];
        mstar = fmaxf(mstar, mc[cgi]);
    }
    float wgt[MAXC], lstar = 0.f;
    for (int cgi = 0; cgi < nc; cgi++) {
        wgt[cgi] = __expf(mc[cgi] - mstar);
        lstar += lc[cgi] * wgt[cgi];
    }
    const float inv = 1.0f / lstar;

    float4 a0 = make_float4(0.f, 0.f, 0.f, 0.f);
    float4 a1 = make_float4(0.f, 0.f, 0.f, 0.f);
    for (int cgi = 0; cgi < nc; cgi++) {
        const float* gp = g_opart + (base + cgi) * 4096 + r * 64 + c8;
        float4 p0 = *(const float4*)gp;
        float4 p1 = *(const float4*)(gp + 4);
        float wv = wgt[cgi];
        a0.x += wv * p0.x; a0.y += wv * p0.y; a0.z += wv * p0.z; a0.w += wv * p0.w;
        a1.x += wv * p1.x; a1.y += wv * p1.y; a1.z += wv * p1.z; a1.w += wv * p1.w;
    }
    float* Ob = out + ((size_t)b * TSEQ + (size_t)q * 64 + r) * HEAD + c8;
    *(float4*)Ob       = make_float4(a0.x * inv, a0.y * inv, a0.z * inv, a0.w * inv);
    *(float4*)(Ob + 4) = make_float4(a1.x * inv, a1.y * inv, a1.z * inv, a1.w * inv);
}

// ---------------------------------------------------------------------------
extern "C" void kernel_launch(void* const* d_in, const int* in_sizes, int n_in,
                              void* d_out, int out_size)
{
    (void)in_sizes; (void)n_in; (void)out_size;
    const float* x  = (const float*)d_in[0];
    const float* Wq = (const float*)d_in[1];
    const float* Wk = (const float*)d_in[2];
    const float* Wv = (const float*)d_in[3];
    float* out = (float*)d_out;

    dim3 pgrid((BATCH * TSEQ) / 64, 3);
    proj_kernel<<<pgrid, 128>>>(x, Wq, Wk, Wv);

    cudaFuncSetAttribute(attn_kernel, cudaFuncAttributeMaxDynamicSharedMemorySize, ATTN_SMEM);
    dim3 grid(UNITS_PER_B, BATCH);
    attn_kernel<<<grid, 128, ATTN_SMEM>>>(out);

    dim3 cgrid(NQT - 8, BATCH, 4);
    combine_kernel<<<cgrid, 128>>>(out);
}